// round 9
// baseline (speedup 1.0000x reference)
#include <cuda_runtime.h>
#include <cstddef>

#define BB 64
#define TT 512
#define DD 1024
#define NN 64
#define SCORES_ELEMS (BB*TT*NN)
#define TAGS_OFF SCORES_ELEMS
#define LOSS_OFF (SCORES_ELEMS + BB*TT)

#define L2E 1.4426950408889634f
#define LN2 0.6931471805599453f

__device__ float g_logz[BB];
__device__ float g_gold[BB];

__device__ __forceinline__ float fast_ex2(float x){ float r; asm("ex2.approx.ftz.f32 %0, %1;" : "=f"(r) : "f"(x)); return r; }
__device__ __forceinline__ float fast_lg2(float x){ float r; asm("lg2.approx.ftz.f32 %0, %1;" : "=f"(r) : "f"(x)); return r; }

typedef unsigned long long ull;
__device__ __forceinline__ ull pk2(float x, float y){ ull r; asm("mov.b64 %0, {%1,%2};" : "=l"(r) : "f"(x), "f"(y)); return r; }
__device__ __forceinline__ void upk2(ull v, float& x, float& y){ asm("mov.b64 {%0,%1}, %2;" : "=f"(x), "=f"(y) : "l"(v)); }
__device__ __forceinline__ ull ffma2(ull a, ull b, ull c){ ull d; asm("fma.rn.f32x2 %0, %1, %2, %3;" : "=l"(d) : "l"(a), "l"(b), "l"(c)); return d; }
__device__ __forceinline__ ull fadd2(ull a, ull b){ ull d; asm("add.rn.f32x2 %0, %1, %2;" : "=l"(d) : "l"(a), "l"(b)); return d; }

// ---------------------------------------------------------------------------
// GEMM (R3 config, measured 152.8us): 256 CTAs x 128 threads, tile 128x64,
// 8x8/thread, f32x2 on column pairs, KC=32 double-buffered.
// ---------------------------------------------------------------------------
#define KC 32
#define NCHUNK (DD/KC)

__global__ __launch_bounds__(128, 3) void gemm_f32x2_kernel(
    const float* __restrict__ X, const float* __restrict__ W,
    const float* __restrict__ bias, const int* __restrict__ mask,
    float* __restrict__ out, float* __restrict__ out_loss)
{
    __shared__ __align__(16) float As[2][KC][128];
    __shared__ __align__(16) float Ws[2][KC][64];

    const int tid = threadIdx.x;
    const int rg = tid >> 3;
    const int cg = tid & 7;
    const int r8 = rg * 8, c8 = cg * 8;
    const int rowbase = blockIdx.x * 128;

    if (blockIdx.x == 0 && tid == 0) *out_loss = 0.f;

    const float* Xrow = X + (size_t)(rowbase + tid) * DD;
    const int kr = tid >> 2;
    const int wsoff = (tid & 3) * 16;

    float4 xa[8], wb[4];
    ull acc[8][4];
    #pragma unroll
    for (int r = 0; r < 8; r++)
        #pragma unroll
        for (int p = 0; p < 4; p++) acc[r][p] = 0ULL;

    #pragma unroll
    for (int q = 0; q < 8; q++) xa[q] = *(const float4*)&Xrow[q * 4];
    #pragma unroll
    for (int e = 0; e < 4; e++) wb[e] = *(const float4*)&W[(size_t)kr * NN + wsoff + e * 4];
    #pragma unroll
    for (int q = 0; q < 8; q++) {
        As[0][q*4+0][tid] = xa[q].x; As[0][q*4+1][tid] = xa[q].y;
        As[0][q*4+2][tid] = xa[q].z; As[0][q*4+3][tid] = xa[q].w;
    }
    #pragma unroll
    for (int e = 0; e < 4; e++) *(float4*)&Ws[0][kr][wsoff + e * 4] = wb[e];
    __syncthreads();

    for (int c = 0; c < NCHUNK; c++) {
        if (c + 1 < NCHUNK) {
            const int kk = (c + 1) * KC;
            #pragma unroll
            for (int q = 0; q < 8; q++) xa[q] = *(const float4*)&Xrow[kk + q * 4];
            #pragma unroll
            for (int e = 0; e < 4; e++) wb[e] = *(const float4*)&W[(size_t)(kk + kr) * NN + wsoff + e * 4];
        }
        const int buf = c & 1;
        #pragma unroll 8
        for (int k = 0; k < KC; k++) {
            float4 a0 = *(const float4*)&As[buf][k][r8];
            float4 a1 = *(const float4*)&As[buf][k][r8 + 4];
            ulonglong2 w0 = *(const ulonglong2*)&Ws[buf][k][c8];
            ulonglong2 w1 = *(const ulonglong2*)&Ws[buf][k][c8 + 4];
            ull A[8];
            A[0] = pk2(a0.x, a0.x); A[1] = pk2(a0.y, a0.y);
            A[2] = pk2(a0.z, a0.z); A[3] = pk2(a0.w, a0.w);
            A[4] = pk2(a1.x, a1.x); A[5] = pk2(a1.y, a1.y);
            A[6] = pk2(a1.z, a1.z); A[7] = pk2(a1.w, a1.w);
            #pragma unroll
            for (int r = 0; r < 8; r++) {
                acc[r][0] = ffma2(A[r], w0.x, acc[r][0]);
                acc[r][1] = ffma2(A[r], w0.y, acc[r][1]);
                acc[r][2] = ffma2(A[r], w1.x, acc[r][2]);
                acc[r][3] = ffma2(A[r], w1.y, acc[r][3]);
            }
        }
        __syncthreads();
        if (c + 1 < NCHUNK) {
            const int nb = (c + 1) & 1;
            #pragma unroll
            for (int q = 0; q < 8; q++) {
                As[nb][q*4+0][tid] = xa[q].x; As[nb][q*4+1][tid] = xa[q].y;
                As[nb][q*4+2][tid] = xa[q].z; As[nb][q*4+3][tid] = xa[q].w;
            }
            #pragma unroll
            for (int e = 0; e < 4; e++) *(float4*)&Ws[nb][kr][wsoff + e * 4] = wb[e];
            __syncthreads();
        }
    }

    float bs[8];
    #pragma unroll
    for (int e = 0; e < 8; e++) bs[e] = bias[c8 + e];
    #pragma unroll
    for (int r = 0; r < 8; r++) {
        const int row = rowbase + r8 + r;
        const float mf = (float)mask[row];
        float v[8];
        upk2(acc[r][0], v[0], v[1]); upk2(acc[r][1], v[2], v[3]);
        upk2(acc[r][2], v[4], v[5]); upk2(acc[r][3], v[6], v[7]);
        float4 o0, o1;
        o0.x = (v[0]+bs[0])*mf; o0.y = (v[1]+bs[1])*mf; o0.z = (v[2]+bs[2])*mf; o0.w = (v[3]+bs[3])*mf;
        o1.x = (v[4]+bs[4])*mf; o1.y = (v[5]+bs[5])*mf; o1.z = (v[6]+bs[6])*mf; o1.w = (v[7]+bs[7])*mf;
        *(float4*)&out[(size_t)row * NN + c8]     = o0;
        *(float4*)&out[(size_t)row * NN + c8 + 4] = o1;
    }
}

// ---------------------------------------------------------------------------
// CRF kernel, 128 threads/CTA.
// Blocks 0..63: LSE on warp 0 (2 tags/lane, barrier-free loop, (p,p) pairs in
//   shared); gold on warp 1 concurrently; warps 2-3 idle.
// Blocks 64..127: Viterbi, 2 thr/tag, pipelined tree argmax, 1 sync/step.
// ---------------------------------------------------------------------------
struct VitSm {
    unsigned char bp[(TT - 1) * NN];
    float alphaS[2][NN];
    int   tag[TT];
};
struct LseSm {
    ull   pdup[2][NN];     // (p,p) duplicated pairs, ping-pong
    float logz_s, gold_s;
};
union CrfSm { VitSm v; LseSm l; };

#define BIGI 0x7fffffff

__global__ __launch_bounds__(128) void crf_kernel(
    const float* __restrict__ scores, const int* __restrict__ mask,
    const int* __restrict__ labels, const float* __restrict__ trans,
    const float* __restrict__ startv, const float* __restrict__ endv,
    float* __restrict__ out_tags, float* __restrict__ out_loss)
{
    __shared__ __align__(16) CrfSm sm;
    const int tid = threadIdx.x;

    if (blockIdx.x < BB) {
        const int b = blockIdx.x;
        const int warp = tid >> 5;
        const int lane = tid & 31;
        if (warp == 0) {
            // ===== LOG PARTITION: single warp, lane owns tags j0=lane, j1=lane+32
            const int j0 = lane, j1 = lane + 32;

            unsigned mkb[TT/32];
            #pragma unroll
            for (int w = 0; w < TT/32; w++)
                mkb[w] = __ballot_sync(0xffffffffu, mask[b * TT + w * 32 + lane] != 0);

            // E2[i] = (exp(trans[i][j0]), exp(trans[i][j1]))
            ull E2[NN];
            #pragma unroll
            for (int i = 0; i < NN; i++) {
                float e0 = fast_ex2(trans[i * NN + j0] * L2E);
                float e1 = fast_ex2(trans[i * NN + j1] * L2E);
                E2[i] = pk2(e0, e1);
            }

            const float* srow0 = scores + (size_t)b * TT * NN + j0;
            const float* srow1 = scores + (size_t)b * TT * NN + j1;
            float alpha0 = startv[j0] + srow0[0];
            float alpha1 = startv[j1] + srow1[0];
            const float m0 = startv[0] + scores[(size_t)b * TT * NN];
            float Mref = m0;
            {
                float p0 = fast_ex2((alpha0 - m0) * L2E);
                float p1 = fast_ex2((alpha1 - m0) * L2E);
                sm.l.pdup[0][j0] = pk2(p0, p0);
                sm.l.pdup[0][j1] = pk2(p1, p1);
            }

            float e0c = srow0[NN],     e1c = srow1[NN];
            float e0n = srow0[2 * NN], e1n = srow1[2 * NN];
            __syncwarp();

            for (int t = 1; t < TT; t++) {
                const int pb = (t - 1) & 1, cb = t & 1;
                // p of tag 0 (broadcast 8B load) for the reference reconstruction
                float p0first, pdum;
                upk2(sm.l.pdup[pb][0], p0first, pdum);
                // matvec: 8 clean blocks of 8 pairs  (indices 0..63 exactly)
                ull a0 = 0ULL, a1 = 0ULL, a2 = 0ULL, a3 = 0ULL;
                ull a4 = 0ULL, a5 = 0ULL, a6 = 0ULL, a7 = 0ULL;
                #pragma unroll
                for (int i = 0; i < NN; i += 8) {
                    ulonglong2 qa = *(const ulonglong2*)&sm.l.pdup[pb][i];
                    ulonglong2 qb = *(const ulonglong2*)&sm.l.pdup[pb][i + 2];
                    ulonglong2 qc = *(const ulonglong2*)&sm.l.pdup[pb][i + 4];
                    ulonglong2 qd = *(const ulonglong2*)&sm.l.pdup[pb][i + 6];
                    a0 = ffma2(qa.x, E2[i + 0], a0); a1 = ffma2(qa.y, E2[i + 1], a1);
                    a2 = ffma2(qb.x, E2[i + 2], a2); a3 = ffma2(qb.y, E2[i + 3], a3);
                    a4 = ffma2(qc.x, E2[i + 4], a4); a5 = ffma2(qc.y, E2[i + 5], a5);
                    a6 = ffma2(qd.x, E2[i + 6], a6); a7 = ffma2(qd.y, E2[i + 7], a7);
                }
                ull s01 = fadd2(fadd2(a0, a1), fadd2(a2, a3));
                ull s23 = fadd2(fadd2(a4, a5), fadd2(a6, a7));
                ull sall = fadd2(s01, s23);
                float s0, s1; upk2(sall, s0, s1);
                const float mNew = fmaf(fast_lg2(p0first), LN2, Mref);  // alpha_0^(t-1)
                float cand0 = fmaf(fast_lg2(s0), LN2, Mref) + e0c;
                float cand1 = fmaf(fast_lg2(s1), LN2, Mref) + e1c;
                const int bit = (mkb[t >> 5] >> (t & 31)) & 1;
                if (bit) { alpha0 = cand0; alpha1 = cand1; }
                float pn0 = fast_ex2((alpha0 - mNew) * L2E);
                float pn1 = fast_ex2((alpha1 - mNew) * L2E);
                sm.l.pdup[cb][j0] = pk2(pn0, pn0);
                sm.l.pdup[cb][j1] = pk2(pn1, pn1);
                Mref = mNew;
                e0c = e0n; e1c = e1n;
                if (t + 2 < TT) {
                    e0n = srow0[(size_t)(t + 2) * NN];
                    e1n = srow1[(size_t)(t + 2) * NN];
                }
                __syncwarp();
            }
            // final logsumexp(alpha + end) within the warp
            float v0 = alpha0 + endv[j0];
            float v1 = alpha1 + endv[j1];
            float m2 = __shfl_sync(0xffffffffu, v0, 0);
            float ss = fast_ex2((v0 - m2) * L2E) + fast_ex2((v1 - m2) * L2E);
            #pragma unroll
            for (int off = 16; off; off >>= 1) ss += __shfl_xor_sync(0xffffffffu, ss, off);
            if (lane == 0) {
                float lz = fmaf(fast_lg2(ss), LN2, m2);
                g_logz[b] = lz;
                sm.l.logz_s = lz;
            }
        } else if (warp == 1) {
            // ============ GOLD SCORE (warp 1, concurrent) ==========
            float acc = 0.f; int cnt = 0;
            for (int t = lane; t < TT; t += 32) {
                const int mkv = mask[b * TT + t];
                const int lt = labels[b * TT + t];
                const float mf = (float)mkv;
                acc += scores[((size_t)(b * TT + t)) * NN + lt] * mf;
                if (t > 0) {
                    const int lp = labels[b * TT + t - 1];
                    acc += trans[lp * NN + lt] * mf;
                }
                cnt += mkv;
            }
            #pragma unroll
            for (int off = 16; off; off >>= 1) {
                acc += __shfl_xor_sync(0xffffffffu, acc, off);
                cnt += __shfl_xor_sync(0xffffffffu, cnt, off);
            }
            if (lane == 0) {
                float gd = acc + startv[labels[b * TT]] + endv[labels[b * TT + cnt - 1]];
                g_gold[b] = gd;
                sm.l.gold_s = gd;
            }
        }
        __syncthreads();
        if (tid == 0)
            atomicAdd(out_loss, (sm.l.logz_s - sm.l.gold_s) * (1.0f / 64.0f));
    } else {
        // ===== VITERBI: 2 thr/tag, pipelined tree argmax, 1 sync/step =======
        const int b = blockIdx.x - BB;
        const int j = tid >> 1;
        const int h = tid & 1;
        const int i0 = h * 32;

        unsigned mkb[TT/32];
        #pragma unroll
        for (int w = 0; w < TT/32; w++)
            mkb[w] = __ballot_sync(0xffffffffu, mask[b * TT + w * 32 + (tid & 31)] != 0);

        float Tr[32];
        #pragma unroll
        for (int i = 0; i < 32; i++) Tr[i] = trans[(i0 + i) * NN + j];

        const float* srow = scores + (size_t)b * TT * NN + j;
        float alpha = 0.f;
        if (h == 0) { alpha = startv[j] + srow[0]; sm.v.alphaS[0][j] = alpha; }
        float ecur = srow[NN];
        float enext = srow[2 * NN];
        __syncthreads();

        for (int t = 1; t < TT; t++) {
            const int pb = (t - 1) & 1, cb = t & 1;
            float v[32];
            #pragma unroll
            for (int c = 0; c < 8; c++) {
                float4 av = *(const float4*)&sm.v.alphaS[pb][i0 + c * 4];
                v[c*4+0] = av.x + Tr[c*4+0];
                v[c*4+1] = av.y + Tr[c*4+1];
                v[c*4+2] = av.z + Tr[c*4+2];
                v[c*4+3] = av.w + Tr[c*4+3];
            }
            // value max: FMNMX tree, depth 5, fully pipelined
            float m16[16], m8[8], m4[4], m2[2];
            #pragma unroll
            for (int i = 0; i < 16; i++) m16[i] = fmaxf(v[i], v[i + 16]);
            #pragma unroll
            for (int i = 0; i < 8; i++)  m8[i] = fmaxf(m16[i], m16[i + 8]);
            #pragma unroll
            for (int i = 0; i < 4; i++)  m4[i] = fmaxf(m8[i], m8[i + 4]);
            m2[0] = fmaxf(m4[0], m4[2]); m2[1] = fmaxf(m4[1], m4[3]);
            const float bm = fmaxf(m2[0], m2[1]);
            // first index equal to max: independent SELs + IMNMX tree
            int e[32];
            #pragma unroll
            for (int i = 0; i < 32; i++) e[i] = (v[i] == bm) ? (i0 + i) : BIGI;
            #pragma unroll
            for (int i = 0; i < 16; i++) e[i] = min(e[i], e[i + 16]);
            #pragma unroll
            for (int i = 0; i < 8; i++)  e[i] = min(e[i], e[i + 8]);
            #pragma unroll
            for (int i = 0; i < 4; i++)  e[i] = min(e[i], e[i + 4]);
            const int idx = min(min(e[0], e[2]), min(e[1], e[3]));
            // merge with partner lane
            const float vo = __shfl_xor_sync(0xffffffffu, bm, 1);
            const int   io = __shfl_xor_sync(0xffffffffu, idx, 1);
            const float bAll = fmaxf(bm, vo);
            const int bi = min((bm == bAll) ? idx : BIGI, (vo == bAll) ? io : BIGI);
            if (h == 0) {
                const int bit = (mkb[t >> 5] >> (t & 31)) & 1;
                sm.v.bp[(t - 1) * NN + j] = (unsigned char)(bit ? bi : j);
                if (bit) alpha = bAll + ecur;
                sm.v.alphaS[cb][j] = alpha;
            }
            ecur = enext;
            if (t + 2 < TT) enext = srow[(size_t)(t + 2) * NN];
            __syncthreads();
        }
        if (tid == 0) {
            const int fb = (TT - 1) & 1;
            float bestf = -1e30f; int cur = 0;
            for (int jj = 0; jj < NN; jj++) {
                float vv = sm.v.alphaS[fb][jj] + endv[jj];
                if (vv > bestf) { bestf = vv; cur = jj; }
            }
            sm.v.tag[TT - 1] = cur;
            for (int t = TT - 1; t >= 1; t--) {
                cur = sm.v.bp[(t - 1) * NN + cur];
                sm.v.tag[t - 1] = cur;
            }
        }
        __syncthreads();
        for (int t = tid; t < TT; t += 128) {
            const int bit = (mkb[t >> 5] >> (t & 31)) & 1;
            out_tags[b * TT + t] = (float)(sm.v.tag[t] * bit);
        }
    }
}

extern "C" void kernel_launch(void* const* d_in, const int* in_sizes, int n_in,
                              void* d_out, int out_size) {
    const float* X      = (const float*)d_in[0];
    const int*   mask   = (const int*)d_in[1];
    const int*   labels = (const int*)d_in[2];
    const float* W      = (const float*)d_in[3];
    const float* bias   = (const float*)d_in[4];
    const float* trans  = (const float*)d_in[5];
    const float* startv = (const float*)d_in[6];
    const float* endv   = (const float*)d_in[7];
    float* out = (float*)d_out;

    gemm_f32x2_kernel<<<256, 128>>>(X, W, bias, mask, out, out + LOSS_OFF);
    crf_kernel<<<128, 128>>>(out, mask, labels, trans, startv, endv,
                             out + TAGS_OFF, out + LOSS_OFF);
}

// round 11
// speedup vs baseline: 1.1264x; 1.1264x over previous
#include <cuda_runtime.h>
#include <cstddef>

#define BB 64
#define TT 512
#define DD 1024
#define NN 64
#define SCORES_ELEMS (BB*TT*NN)
#define TAGS_OFF SCORES_ELEMS
#define LOSS_OFF (SCORES_ELEMS + BB*TT)

#define L2E 1.4426950408889634f
#define LN2 0.6931471805599453f

__device__ float g_logz[BB];
__device__ float g_gold[BB];
__device__ __align__(16) float g_part[SCORES_ELEMS];   // split-K partial (8MB)

__device__ __forceinline__ float fast_ex2(float x){ float r; asm("ex2.approx.ftz.f32 %0, %1;" : "=f"(r) : "f"(x)); return r; }
__device__ __forceinline__ float fast_lg2(float x){ float r; asm("lg2.approx.ftz.f32 %0, %1;" : "=f"(r) : "f"(x)); return r; }

typedef unsigned long long ull;
__device__ __forceinline__ ull pk2(float x, float y){ ull r; asm("mov.b64 %0, {%1,%2};" : "=l"(r) : "f"(x), "f"(y)); return r; }
__device__ __forceinline__ void upk2(ull v, float& x, float& y){ asm("mov.b64 {%0,%1}, %2;" : "=f"(x), "=f"(y) : "l"(v)); }
__device__ __forceinline__ ull ffma2(ull a, ull b, ull c){ ull d; asm("fma.rn.f32x2 %0, %1, %2, %3;" : "=l"(d) : "l"(a), "l"(b), "l"(c)); return d; }

__device__ __forceinline__ void bar1_64(){ asm volatile("bar.sync 1, 64;" ::: "memory"); }
__device__ __forceinline__ void bar2_64(){ asm volatile("bar.sync 2, 64;" ::: "memory"); }

// ---------------------------------------------------------------------------
// Split-K GEMM with f32x2 dual-FMA (R4 config — best measured GEMM path).
// grid = 512: blockIdx.x = rowtile*2 + split. Each CTA: 128 rows x 64 cols,
// K-range [split*512, split*512+512). Raw partials: split0 -> out, split1 ->
// g_part. One __syncthreads per K-chunk steady-state.
// ---------------------------------------------------------------------------
#define KC 32
#define KSPLIT 512
#define NCHUNK (KSPLIT/KC)

__global__ __launch_bounds__(128, 3) void gemm_f32x2_kernel(
    const float* __restrict__ X, const float* __restrict__ W,
    float* __restrict__ out, float* __restrict__ out_loss)
{
    __shared__ __align__(16) float As[2][KC][128];   // 32768 B
    __shared__ __align__(16) float Ws[2][KC][64];    // 16384 B

    const int tid = threadIdx.x;
    const int split = blockIdx.x & 1;
    const int rowtile = blockIdx.x >> 1;
    const int rowbase = rowtile * 128;
    const int kbase = split * KSPLIT;

    if (blockIdx.x == 0 && tid == 0) *out_loss = 0.f;

    const int rg = tid >> 3;        // 0..15
    const int cg = tid & 7;         // 0..7
    const int r8 = rg * 8, c8 = cg * 8;

    const float* Xrow = X + (size_t)(rowbase + tid) * DD + kbase;
    const int kr = tid >> 2;            // 0..31
    const int wsoff = (tid & 3) * 16;   // 0,16,32,48
    const float* Wbase = W + (size_t)(kbase + kr) * NN + wsoff;

    float4 xa[8], wb[4];

    ull acc[8][4];
    #pragma unroll
    for (int r = 0; r < 8; r++)
        #pragma unroll
        for (int p = 0; p < 4; p++) acc[r][p] = 0ULL;

    // prologue: chunk 0
    #pragma unroll
    for (int q = 0; q < 8; q++) xa[q] = *(const float4*)&Xrow[q * 4];
    #pragma unroll
    for (int e = 0; e < 4; e++) wb[e] = *(const float4*)&Wbase[e * 4];
    #pragma unroll
    for (int q = 0; q < 8; q++) {
        As[0][q*4+0][tid] = xa[q].x; As[0][q*4+1][tid] = xa[q].y;
        As[0][q*4+2][tid] = xa[q].z; As[0][q*4+3][tid] = xa[q].w;
    }
    #pragma unroll
    for (int e = 0; e < 4; e++) *(float4*)&Ws[0][kr][wsoff + e * 4] = wb[e];
    __syncthreads();

    for (int c = 0; c < NCHUNK; c++) {
        if (c + 1 < NCHUNK) {
            const int kk = (c + 1) * KC;
            #pragma unroll
            for (int q = 0; q < 8; q++) xa[q] = *(const float4*)&Xrow[kk + q * 4];
            #pragma unroll
            for (int e = 0; e < 4; e++) wb[e] = *(const float4*)&Wbase[(size_t)kk * NN + e * 4];
        }
        const int buf = c & 1;
        #pragma unroll 8
        for (int k = 0; k < KC; k++) {
            float4 a0 = *(const float4*)&As[buf][k][r8];
            float4 a1 = *(const float4*)&As[buf][k][r8 + 4];
            ulonglong2 w0 = *(const ulonglong2*)&Ws[buf][k][c8];
            ulonglong2 w1 = *(const ulonglong2*)&Ws[buf][k][c8 + 4];
            ull A[8];
            A[0] = pk2(a0.x, a0.x); A[1] = pk2(a0.y, a0.y);
            A[2] = pk2(a0.z, a0.z); A[3] = pk2(a0.w, a0.w);
            A[4] = pk2(a1.x, a1.x); A[5] = pk2(a1.y, a1.y);
            A[6] = pk2(a1.z, a1.z); A[7] = pk2(a1.w, a1.w);
            #pragma unroll
            for (int r = 0; r < 8; r++) {
                acc[r][0] = ffma2(A[r], w0.x, acc[r][0]);
                acc[r][1] = ffma2(A[r], w0.y, acc[r][1]);
                acc[r][2] = ffma2(A[r], w1.x, acc[r][2]);
                acc[r][3] = ffma2(A[r], w1.y, acc[r][3]);
            }
        }
        if (c + 1 < NCHUNK) {
            const int nb = (c + 1) & 1;
            #pragma unroll
            for (int q = 0; q < 8; q++) {
                As[nb][q*4+0][tid] = xa[q].x; As[nb][q*4+1][tid] = xa[q].y;
                As[nb][q*4+2][tid] = xa[q].z; As[nb][q*4+3][tid] = xa[q].w;
            }
            #pragma unroll
            for (int e = 0; e < 4; e++) *(float4*)&Ws[nb][kr][wsoff + e * 4] = wb[e];
            __syncthreads();
        }
    }

    float* dst = split ? g_part : out;
    #pragma unroll
    for (int r = 0; r < 8; r++) {
        const int row = rowbase + r8 + r;
        float v[8];
        upk2(acc[r][0], v[0], v[1]); upk2(acc[r][1], v[2], v[3]);
        upk2(acc[r][2], v[4], v[5]); upk2(acc[r][3], v[6], v[7]);
        float4 o0 = { v[0], v[1], v[2], v[3] };
        float4 o1 = { v[4], v[5], v[6], v[7] };
        *(float4*)&dst[(size_t)row * NN + c8]     = o0;
        *(float4*)&dst[(size_t)row * NN + c8 + 4] = o1;
    }
}

// out = (out + g_part + bias) * mask   (524288 float4s)
__global__ __launch_bounds__(256) void reduce_kernel(
    const float* __restrict__ bias, const int* __restrict__ mask,
    float* __restrict__ out)
{
    const int i = blockIdx.x * 256 + threadIdx.x;     // float4 index
    float4 a = ((const float4*)out)[i];
    float4 p = ((const float4*)g_part)[i];
    const int row = i >> 4;
    const float mf = (float)mask[row];
    const int c4 = (i & 15) * 4;
    float4 bv = *(const float4*)&bias[c4];
    float4 o;
    o.x = (a.x + p.x + bv.x) * mf;
    o.y = (a.y + p.y + bv.y) * mf;
    o.z = (a.z + p.z + bv.z) * mf;
    o.w = (a.w + p.w + bv.w) * mf;
    ((float4*)out)[i] = o;
}

// ---------------------------------------------------------------------------
// CRF kernel, 128 threads/CTA.
// Blocks 0..63: LSE (threads 0-63, f32x2 matvec, 1 named bar/step) + gold
//   (threads 64-127, concurrent) + fused loss.
// Blocks 64..127: Viterbi, 2 thr/tag, pipelined FMNMX/IMNMX tree argmax.
// ---------------------------------------------------------------------------
struct VitSm {
    unsigned char bp[(TT - 1) * NN];
    float alphaS[2][NN];
    int   tag[TT];
};
struct LseSm {
    float pS[2][NN];
    float redf[2];
    int   redi[2];
    float logz_s, gold_s;
};
union CrfSm { VitSm v; LseSm l; };

#define BIGI 0x7fffffff

__global__ __launch_bounds__(128) void crf_kernel(
    const float* __restrict__ scores, const int* __restrict__ mask,
    const int* __restrict__ labels, const float* __restrict__ trans,
    const float* __restrict__ startv, const float* __restrict__ endv,
    float* __restrict__ out_tags, float* __restrict__ out_loss)
{
    __shared__ __align__(16) CrfSm sm;
    const int tid = threadIdx.x;

    if (blockIdx.x < BB) {
        const int b = blockIdx.x;
        if (tid < 64) {
            // ============ LOG PARTITION (threads 0..63, 1 thread/tag) =======
            const int j = tid;
            unsigned mkb[TT/32];
            #pragma unroll
            for (int w = 0; w < TT/32; w++)
                mkb[w] = __ballot_sync(0xffffffffu, mask[b * TT + w * 32 + (tid & 31)] != 0);

            // E packed in f32x2 pairs over source tags (32 u64 regs)
            ull E2[NN/2];
            #pragma unroll
            for (int i2 = 0; i2 < NN/2; i2++) {
                float e0 = fast_ex2(trans[(2*i2)     * NN + j] * L2E);
                float e1 = fast_ex2(trans[(2*i2 + 1) * NN + j] * L2E);
                E2[i2] = pk2(e0, e1);
            }

            const float* srow = scores + (size_t)b * TT * NN + j;
            float alpha = startv[j] + srow[0];
            const float m0 = startv[0] + scores[(size_t)b * TT * NN];
            float Mref = m0;
            sm.l.pS[0][j] = fast_ex2((alpha - m0) * L2E);

            float ecur = srow[NN];
            float enext = srow[2 * NN];
            bar1_64();

            for (int t = 1; t < TT; t++) {
                const int pb = (t - 1) & 1, cb = t & 1;
                float p0 = sm.l.pS[pb][0];
                const float mNew = fmaf(fast_lg2(p0), LN2, Mref);   // alpha0^(t-1)
                ull a0 = 0ULL, a1 = 0ULL, a2 = 0ULL, a3 = 0ULL;
                #pragma unroll
                for (int i = 0; i < NN; i += 8) {
                    ulonglong2 q0 = *(const ulonglong2*)&sm.l.pS[pb][i];
                    ulonglong2 q1 = *(const ulonglong2*)&sm.l.pS[pb][i + 4];
                    a0 = ffma2(q0.x, E2[i/2],     a0);
                    a1 = ffma2(q0.y, E2[i/2 + 1], a1);
                    a2 = ffma2(q1.x, E2[i/2 + 2], a2);
                    a3 = ffma2(q1.y, E2[i/2 + 3], a3);
                }
                float f0,f1,f2,f3,f4,f5,f6,f7;
                upk2(a0,f0,f1); upk2(a1,f2,f3); upk2(a2,f4,f5); upk2(a3,f6,f7);
                float s = ((f0+f1)+(f2+f3)) + ((f4+f5)+(f6+f7));
                float cand = fmaf(fast_lg2(s), LN2, Mref) + ecur;
                const int bit = (mkb[t >> 5] >> (t & 31)) & 1;
                if (bit) alpha = cand;
                sm.l.pS[cb][j] = fast_ex2((alpha - mNew) * L2E);
                Mref = mNew;
                ecur = enext;
                if (t + 2 < TT) enext = srow[(size_t)(t + 2) * NN];
                bar1_64();
            }
            sm.l.pS[0][j] = alpha + endv[j];
            bar1_64();
            if (tid < 32) {
                float v0 = sm.l.pS[0][tid], v1 = sm.l.pS[0][tid + 32];
                float m2 = sm.l.pS[0][0];
                float ss = fast_ex2((v0 - m2) * L2E) + fast_ex2((v1 - m2) * L2E);
                #pragma unroll
                for (int off = 16; off; off >>= 1) ss += __shfl_xor_sync(0xffffffffu, ss, off);
                if (tid == 0) {
                    float lz = fmaf(fast_lg2(ss), LN2, m2);
                    g_logz[b] = lz;
                    sm.l.logz_s = lz;
                }
            }
        } else {
            // ============ GOLD SCORE (threads 64..127, concurrent) ==========
            const int gt = tid - 64;
            float acc = 0.f; int cnt = 0;
            for (int t = gt; t < TT; t += 64) {
                const int mkv = mask[b * TT + t];
                const int lt = labels[b * TT + t];
                const float mf = (float)mkv;
                acc += scores[((size_t)(b * TT + t)) * NN + lt] * mf;
                if (t > 0) {
                    const int lp = labels[b * TT + t - 1];
                    acc += trans[lp * NN + lt] * mf;
                }
                cnt += mkv;
            }
            #pragma unroll
            for (int off = 16; off; off >>= 1) {
                acc += __shfl_xor_sync(0xffffffffu, acc, off);
                cnt += __shfl_xor_sync(0xffffffffu, cnt, off);
            }
            if ((gt & 31) == 0) { sm.l.redf[gt >> 5] = acc; sm.l.redi[gt >> 5] = cnt; }
            bar2_64();
            if (gt == 0) {
                float a = sm.l.redf[0] + sm.l.redf[1];
                int c = sm.l.redi[0] + sm.l.redi[1];
                float gd = a + startv[labels[b * TT]] + endv[labels[b * TT + c - 1]];
                g_gold[b] = gd;
                sm.l.gold_s = gd;
            }
        }
        __syncthreads();
        if (tid == 0)
            atomicAdd(out_loss, (sm.l.logz_s - sm.l.gold_s) * (1.0f / 64.0f));
    } else {
        // ===== VITERBI: 2 thr/tag, pipelined tree argmax (verified in R8) ===
        const int b = blockIdx.x - BB;
        const int j = tid >> 1;
        const int h = tid & 1;
        const int i0 = h * 32;

        unsigned mkb[TT/32];
        #pragma unroll
        for (int w = 0; w < TT/32; w++)
            mkb[w] = __ballot_sync(0xffffffffu, mask[b * TT + w * 32 + (tid & 31)] != 0);

        float Tr[32];
        #pragma unroll
        for (int i = 0; i < 32; i++) Tr[i] = trans[(i0 + i) * NN + j];

        const float* srow = scores + (size_t)b * TT * NN + j;
        float alpha = 0.f;
        if (h == 0) { alpha = startv[j] + srow[0]; sm.v.alphaS[0][j] = alpha; }
        float ecur = srow[NN];
        float enext = srow[2 * NN];
        __syncthreads();

        for (int t = 1; t < TT; t++) {
            const int pb = (t - 1) & 1, cb = t & 1;
            float v[32];
            #pragma unroll
            for (int c = 0; c < 8; c++) {
                float4 av = *(const float4*)&sm.v.alphaS[pb][i0 + c * 4];
                v[c*4+0] = av.x + Tr[c*4+0];
                v[c*4+1] = av.y + Tr[c*4+1];
                v[c*4+2] = av.z + Tr[c*4+2];
                v[c*4+3] = av.w + Tr[c*4+3];
            }
            // value max: FMNMX tree, depth 5, fully pipelined
            float m16[16], m8[8], m4[4], m2[2];
            #pragma unroll
            for (int i = 0; i < 16; i++) m16[i] = fmaxf(v[i], v[i + 16]);
            #pragma unroll
            for (int i = 0; i < 8; i++)  m8[i] = fmaxf(m16[i], m16[i + 8]);
            #pragma unroll
            for (int i = 0; i < 4; i++)  m4[i] = fmaxf(m8[i], m8[i + 4]);
            m2[0] = fmaxf(m4[0], m4[2]); m2[1] = fmaxf(m4[1], m4[3]);
            const float bm = fmaxf(m2[0], m2[1]);
            // first index equal to max: independent SELs + IMNMX tree
            int e[32];
            #pragma unroll
            for (int i = 0; i < 32; i++) e[i] = (v[i] == bm) ? (i0 + i) : BIGI;
            #pragma unroll
            for (int i = 0; i < 16; i++) e[i] = min(e[i], e[i + 16]);
            #pragma unroll
            for (int i = 0; i < 8; i++)  e[i] = min(e[i], e[i + 8]);
            #pragma unroll
            for (int i = 0; i < 4; i++)  e[i] = min(e[i], e[i + 4]);
            const int idx = min(min(e[0], e[2]), min(e[1], e[3]));
            // merge with partner lane
            const float vo = __shfl_xor_sync(0xffffffffu, bm, 1);
            const int   io = __shfl_xor_sync(0xffffffffu, idx, 1);
            const float bAll = fmaxf(bm, vo);
            const int bi = min((bm == bAll) ? idx : BIGI, (vo == bAll) ? io : BIGI);
            if (h == 0) {
                const int bit = (mkb[t >> 5] >> (t & 31)) & 1;
                sm.v.bp[(t - 1) * NN + j] = (unsigned char)(bit ? bi : j);
                if (bit) alpha = bAll + ecur;
                sm.v.alphaS[cb][j] = alpha;
            }
            ecur = enext;
            if (t + 2 < TT) enext = srow[(size_t)(t + 2) * NN];
            __syncthreads();
        }
        if (tid == 0) {
            const int fb = (TT - 1) & 1;
            float bestf = -1e30f; int cur = 0;
            for (int jj = 0; jj < NN; jj++) {
                float vv = sm.v.alphaS[fb][jj] + endv[jj];
                if (vv > bestf) { bestf = vv; cur = jj; }
            }
            sm.v.tag[TT - 1] = cur;
            for (int t = TT - 1; t >= 1; t--) {
                cur = sm.v.bp[(t - 1) * NN + cur];
                sm.v.tag[t - 1] = cur;
            }
        }
        __syncthreads();
        for (int t = tid; t < TT; t += 128) {
            const int bit = (mkb[t >> 5] >> (t & 31)) & 1;
            out_tags[b * TT + t] = (float)(sm.v.tag[t] * bit);
        }
    }
}

extern "C" void kernel_launch(void* const* d_in, const int* in_sizes, int n_in,
                              void* d_out, int out_size) {
    const float* X      = (const float*)d_in[0];
    const int*   mask   = (const int*)d_in[1];
    const int*   labels = (const int*)d_in[2];
    const float* W      = (const float*)d_in[3];
    const float* bias   = (const float*)d_in[4];
    const float* trans  = (const float*)d_in[5];
    const float* startv = (const float*)d_in[6];
    const float* endv   = (const float*)d_in[7];
    float* out = (float*)d_out;

    gemm_f32x2_kernel<<<512, 128>>>(X, W, out, out + LOSS_OFF);
    reduce_kernel<<<SCORES_ELEMS / 4 / 256, 256>>>(bias, mask, out);
    crf_kernel<<<128, 128>>>(out, mask, labels, trans, startv, endv,
                             out + TAGS_OFF, out + LOSS_OFF);
}

// round 12
// speedup vs baseline: 1.1395x; 1.0116x over previous
#include <cuda_runtime.h>
#include <cstddef>

#define BB 64
#define TT 512
#define DD 1024
#define NN 64
#define SCORES_ELEMS (BB*TT*NN)
#define TAGS_OFF SCORES_ELEMS
#define LOSS_OFF (SCORES_ELEMS + BB*TT)

#define L2E 1.4426950408889634f
#define LN2 0.6931471805599453f

__device__ float g_logz[BB];
__device__ float g_gold[BB];
__device__ __align__(16) float g_part[SCORES_ELEMS];   // split-K partial (8MB)

__device__ __forceinline__ float fast_ex2(float x){ float r; asm("ex2.approx.ftz.f32 %0, %1;" : "=f"(r) : "f"(x)); return r; }
__device__ __forceinline__ float fast_lg2(float x){ float r; asm("lg2.approx.ftz.f32 %0, %1;" : "=f"(r) : "f"(x)); return r; }

typedef unsigned long long ull;
__device__ __forceinline__ ull pk2(float x, float y){ ull r; asm("mov.b64 %0, {%1,%2};" : "=l"(r) : "f"(x), "f"(y)); return r; }
__device__ __forceinline__ void upk2(ull v, float& x, float& y){ asm("mov.b64 {%0,%1}, %2;" : "=f"(x), "=f"(y) : "l"(v)); }
__device__ __forceinline__ ull ffma2(ull a, ull b, ull c){ ull d; asm("fma.rn.f32x2 %0, %1, %2, %3;" : "=l"(d) : "l"(a), "l"(b), "l"(c)); return d; }

__device__ __forceinline__ void bar1_64(){ asm volatile("bar.sync 1, 64;" ::: "memory"); }
__device__ __forceinline__ void bar2_64(){ asm volatile("bar.sync 2, 64;" ::: "memory"); }

// ---------------------------------------------------------------------------
// Split-K GEMM with f32x2 dual-FMA, KC=16 for 4 CTAs/SM occupancy.
// grid = 512: blockIdx.x = rowtile*2 + split. Each CTA: 128 rows x 64 cols,
// K-range [split*512, ...+512). Raw partials: split0 -> out, split1 -> g_part.
// One __syncthreads per K-chunk steady-state.
// ---------------------------------------------------------------------------
#define KC 16
#define KSPLIT 512
#define NCHUNK (KSPLIT/KC)

__global__ __launch_bounds__(128, 4) void gemm_f32x2_kernel(
    const float* __restrict__ X, const float* __restrict__ W,
    float* __restrict__ out, float* __restrict__ out_loss)
{
    __shared__ __align__(16) float As[2][KC][128];   // 16384 B
    __shared__ __align__(16) float Ws[2][KC][64];    // 8192 B

    const int tid = threadIdx.x;
    const int split = blockIdx.x & 1;
    const int rowtile = blockIdx.x >> 1;
    const int rowbase = rowtile * 128;
    const int kbase = split * KSPLIT;

    if (blockIdx.x == 0 && tid == 0) *out_loss = 0.f;

    const int rg = tid >> 3;        // 0..15
    const int cg = tid & 7;         // 0..7
    const int r8 = rg * 8, c8 = cg * 8;

    const float* Xrow = X + (size_t)(rowbase + tid) * DD + kbase;
    const int kr = tid >> 3;            // 0..15
    const int wsoff = (tid & 7) * 8;    // 0..56
    const float* Wbase = W + (size_t)(kbase + kr) * NN + wsoff;

    float4 xa[4], wb[2];

    ull acc[8][4];
    #pragma unroll
    for (int r = 0; r < 8; r++)
        #pragma unroll
        for (int p = 0; p < 4; p++) acc[r][p] = 0ULL;

    // prologue: chunk 0
    #pragma unroll
    for (int q = 0; q < 4; q++) xa[q] = *(const float4*)&Xrow[q * 4];
    #pragma unroll
    for (int e = 0; e < 2; e++) wb[e] = *(const float4*)&Wbase[e * 4];
    #pragma unroll
    for (int q = 0; q < 4; q++) {
        As[0][q*4+0][tid] = xa[q].x; As[0][q*4+1][tid] = xa[q].y;
        As[0][q*4+2][tid] = xa[q].z; As[0][q*4+3][tid] = xa[q].w;
    }
    #pragma unroll
    for (int e = 0; e < 2; e++) *(float4*)&Ws[0][kr][wsoff + e * 4] = wb[e];
    __syncthreads();

    for (int c = 0; c < NCHUNK; c++) {
        if (c + 1 < NCHUNK) {
            const int kk = (c + 1) * KC;
            #pragma unroll
            for (int q = 0; q < 4; q++) xa[q] = *(const float4*)&Xrow[kk + q * 4];
            #pragma unroll
            for (int e = 0; e < 2; e++) wb[e] = *(const float4*)&Wbase[(size_t)kk * NN + e * 4];
        }
        const int buf = c & 1;
        #pragma unroll 8
        for (int k = 0; k < KC; k++) {
            float4 a0 = *(const float4*)&As[buf][k][r8];
            float4 a1 = *(const float4*)&As[buf][k][r8 + 4];
            ulonglong2 w0 = *(const ulonglong2*)&Ws[buf][k][c8];
            ulonglong2 w1 = *(const ulonglong2*)&Ws[buf][k][c8 + 4];
            ull A[8];
            A[0] = pk2(a0.x, a0.x); A[1] = pk2(a0.y, a0.y);
            A[2] = pk2(a0.z, a0.z); A[3] = pk2(a0.w, a0.w);
            A[4] = pk2(a1.x, a1.x); A[5] = pk2(a1.y, a1.y);
            A[6] = pk2(a1.z, a1.z); A[7] = pk2(a1.w, a1.w);
            #pragma unroll
            for (int r = 0; r < 8; r++) {
                acc[r][0] = ffma2(A[r], w0.x, acc[r][0]);
                acc[r][1] = ffma2(A[r], w0.y, acc[r][1]);
                acc[r][2] = ffma2(A[r], w1.x, acc[r][2]);
                acc[r][3] = ffma2(A[r], w1.y, acc[r][3]);
            }
        }
        if (c + 1 < NCHUNK) {
            const int nb = (c + 1) & 1;
            // safe: buffer nb was last read in iter c-1, all readers passed the
            // sync at the end of c-1; stores land before this chunk's sync.
            #pragma unroll
            for (int q = 0; q < 4; q++) {
                As[nb][q*4+0][tid] = xa[q].x; As[nb][q*4+1][tid] = xa[q].y;
                As[nb][q*4+2][tid] = xa[q].z; As[nb][q*4+3][tid] = xa[q].w;
            }
            #pragma unroll
            for (int e = 0; e < 2; e++) *(float4*)&Ws[nb][kr][wsoff + e * 4] = wb[e];
            __syncthreads();
        }
    }

    float* dst = split ? g_part : out;
    #pragma unroll
    for (int r = 0; r < 8; r++) {
        const int row = rowbase + r8 + r;
        float v[8];
        upk2(acc[r][0], v[0], v[1]); upk2(acc[r][1], v[2], v[3]);
        upk2(acc[r][2], v[4], v[5]); upk2(acc[r][3], v[6], v[7]);
        float4 o0 = { v[0], v[1], v[2], v[3] };
        float4 o1 = { v[4], v[5], v[6], v[7] };
        *(float4*)&dst[(size_t)row * NN + c8]     = o0;
        *(float4*)&dst[(size_t)row * NN + c8 + 4] = o1;
    }
}

// out = (out + g_part + bias) * mask   (524288 float4s)
__global__ __launch_bounds__(256) void reduce_kernel(
    const float* __restrict__ bias, const int* __restrict__ mask,
    float* __restrict__ out)
{
    const int i = blockIdx.x * 256 + threadIdx.x;     // float4 index
    float4 a = ((const float4*)out)[i];
    float4 p = ((const float4*)g_part)[i];
    const int row = i >> 4;
    const float mf = (float)mask[row];
    const int c4 = (i & 15) * 4;
    float4 bv = *(const float4*)&bias[c4];
    float4 o;
    o.x = (a.x + p.x + bv.x) * mf;
    o.y = (a.y + p.y + bv.y) * mf;
    o.z = (a.z + p.z + bv.z) * mf;
    o.w = (a.w + p.w + bv.w) * mf;
    ((float4*)out)[i] = o;
}

// ---------------------------------------------------------------------------
// CRF kernel, 128 threads/CTA.
// Blocks 0..63: LSE (threads 0-63, f32x2 matvec, 1 named bar/step) + gold
//   (threads 64-127, concurrent) + fused loss.
// Blocks 64..127: Viterbi, 2 thr/tag, tree argmax, BRANCHLESS step epilogue
//   (both half-threads hold identical merged results and store them).
// ---------------------------------------------------------------------------
struct VitSm {
    unsigned char bp[(TT - 1) * NN];
    float alphaS[2][NN];
    int   tag[TT];
};
struct LseSm {
    float pS[2][NN];
    float redf[2];
    int   redi[2];
    float logz_s, gold_s;
};
union CrfSm { VitSm v; LseSm l; };

#define BIGI 0x7fffffff

__global__ __launch_bounds__(128) void crf_kernel(
    const float* __restrict__ scores, const int* __restrict__ mask,
    const int* __restrict__ labels, const float* __restrict__ trans,
    const float* __restrict__ startv, const float* __restrict__ endv,
    float* __restrict__ out_tags, float* __restrict__ out_loss)
{
    __shared__ __align__(16) CrfSm sm;
    const int tid = threadIdx.x;

    if (blockIdx.x < BB) {
        const int b = blockIdx.x;
        if (tid < 64) {
            // ============ LOG PARTITION (threads 0..63, 1 thread/tag) =======
            const int j = tid;
            unsigned mkb[TT/32];
            #pragma unroll
            for (int w = 0; w < TT/32; w++)
                mkb[w] = __ballot_sync(0xffffffffu, mask[b * TT + w * 32 + (tid & 31)] != 0);

            // E packed in f32x2 pairs over source tags (32 u64 regs)
            ull E2[NN/2];
            #pragma unroll
            for (int i2 = 0; i2 < NN/2; i2++) {
                float e0 = fast_ex2(trans[(2*i2)     * NN + j] * L2E);
                float e1 = fast_ex2(trans[(2*i2 + 1) * NN + j] * L2E);
                E2[i2] = pk2(e0, e1);
            }

            const float* srow = scores + (size_t)b * TT * NN + j;
            float alpha = startv[j] + srow[0];
            const float m0 = startv[0] + scores[(size_t)b * TT * NN];
            float Mref = m0;
            sm.l.pS[0][j] = fast_ex2((alpha - m0) * L2E);

            float ecur = srow[NN];
            float enext = srow[2 * NN];
            bar1_64();

            for (int t = 1; t < TT; t++) {
                const int pb = (t - 1) & 1, cb = t & 1;
                float p0 = sm.l.pS[pb][0];
                const float mNew = fmaf(fast_lg2(p0), LN2, Mref);   // alpha0^(t-1)
                ull a0 = 0ULL, a1 = 0ULL, a2 = 0ULL, a3 = 0ULL;
                #pragma unroll
                for (int i = 0; i < NN; i += 8) {
                    ulonglong2 q0 = *(const ulonglong2*)&sm.l.pS[pb][i];
                    ulonglong2 q1 = *(const ulonglong2*)&sm.l.pS[pb][i + 4];
                    a0 = ffma2(q0.x, E2[i/2],     a0);
                    a1 = ffma2(q0.y, E2[i/2 + 1], a1);
                    a2 = ffma2(q1.x, E2[i/2 + 2], a2);
                    a3 = ffma2(q1.y, E2[i/2 + 3], a3);
                }
                float f0,f1,f2,f3,f4,f5,f6,f7;
                upk2(a0,f0,f1); upk2(a1,f2,f3); upk2(a2,f4,f5); upk2(a3,f6,f7);
                float s = ((f0+f1)+(f2+f3)) + ((f4+f5)+(f6+f7));
                float cand = fmaf(fast_lg2(s), LN2, Mref) + ecur;
                const int bit = (mkb[t >> 5] >> (t & 31)) & 1;
                if (bit) alpha = cand;
                sm.l.pS[cb][j] = fast_ex2((alpha - mNew) * L2E);
                Mref = mNew;
                ecur = enext;
                if (t + 2 < TT) enext = srow[(size_t)(t + 2) * NN];
                bar1_64();
            }
            sm.l.pS[0][j] = alpha + endv[j];
            bar1_64();
            if (tid < 32) {
                float v0 = sm.l.pS[0][tid], v1 = sm.l.pS[0][tid + 32];
                float m2 = sm.l.pS[0][0];
                float ss = fast_ex2((v0 - m2) * L2E) + fast_ex2((v1 - m2) * L2E);
                #pragma unroll
                for (int off = 16; off; off >>= 1) ss += __shfl_xor_sync(0xffffffffu, ss, off);
                if (tid == 0) {
                    float lz = fmaf(fast_lg2(ss), LN2, m2);
                    g_logz[b] = lz;
                    sm.l.logz_s = lz;
                }
            }
        } else {
            // ============ GOLD SCORE (threads 64..127, concurrent) ==========
            const int gt = tid - 64;
            float acc = 0.f; int cnt = 0;
            for (int t = gt; t < TT; t += 64) {
                const int mkv = mask[b * TT + t];
                const int lt = labels[b * TT + t];
                const float mf = (float)mkv;
                acc += scores[((size_t)(b * TT + t)) * NN + lt] * mf;
                if (t > 0) {
                    const int lp = labels[b * TT + t - 1];
                    acc += trans[lp * NN + lt] * mf;
                }
                cnt += mkv;
            }
            #pragma unroll
            for (int off = 16; off; off >>= 1) {
                acc += __shfl_xor_sync(0xffffffffu, acc, off);
                cnt += __shfl_xor_sync(0xffffffffu, cnt, off);
            }
            if ((gt & 31) == 0) { sm.l.redf[gt >> 5] = acc; sm.l.redi[gt >> 5] = cnt; }
            bar2_64();
            if (gt == 0) {
                float a = sm.l.redf[0] + sm.l.redf[1];
                int c = sm.l.redi[0] + sm.l.redi[1];
                float gd = a + startv[labels[b * TT]] + endv[labels[b * TT + c - 1]];
                g_gold[b] = gd;
                sm.l.gold_s = gd;
            }
        }
        __syncthreads();
        if (tid == 0)
            atomicAdd(out_loss, (sm.l.logz_s - sm.l.gold_s) * (1.0f / 64.0f));
    } else {
        // ===== VITERBI: 2 thr/tag, tree argmax, branchless epilogue =========
        const int b = blockIdx.x - BB;
        const int j = tid >> 1;
        const int h = tid & 1;
        const int i0 = h * 32;

        unsigned mkb[TT/32];
        #pragma unroll
        for (int w = 0; w < TT/32; w++)
            mkb[w] = __ballot_sync(0xffffffffu, mask[b * TT + w * 32 + (tid & 31)] != 0);

        float Tr[32];
        #pragma unroll
        for (int i = 0; i < 32; i++) Tr[i] = trans[(i0 + i) * NN + j];

        const float* srow = scores + (size_t)b * TT * NN + j;
        // BOTH half-threads track alpha (identical values; same-addr stores)
        float alpha = startv[j] + srow[0];
        sm.v.alphaS[0][j] = alpha;
        float ecur = srow[NN];
        float enext = srow[2 * NN];
        __syncthreads();

        for (int t = 1; t < TT; t++) {
            const int pb = (t - 1) & 1, cb = t & 1;
            float v[32];
            #pragma unroll
            for (int c = 0; c < 8; c++) {
                float4 av = *(const float4*)&sm.v.alphaS[pb][i0 + c * 4];
                v[c*4+0] = av.x + Tr[c*4+0];
                v[c*4+1] = av.y + Tr[c*4+1];
                v[c*4+2] = av.z + Tr[c*4+2];
                v[c*4+3] = av.w + Tr[c*4+3];
            }
            // value max: FMNMX tree, depth 5, fully pipelined
            float m16[16], m8[8], m4[4], m2[2];
            #pragma unroll
            for (int i = 0; i < 16; i++) m16[i] = fmaxf(v[i], v[i + 16]);
            #pragma unroll
            for (int i = 0; i < 8; i++)  m8[i] = fmaxf(m16[i], m16[i + 8]);
            #pragma unroll
            for (int i = 0; i < 4; i++)  m4[i] = fmaxf(m8[i], m8[i + 4]);
            m2[0] = fmaxf(m4[0], m4[2]); m2[1] = fmaxf(m4[1], m4[3]);
            const float bm = fmaxf(m2[0], m2[1]);
            // first index equal to max: independent SELs + IMNMX tree
            int e[32];
            #pragma unroll
            for (int i = 0; i < 32; i++) e[i] = (v[i] == bm) ? (i0 + i) : BIGI;
            #pragma unroll
            for (int i = 0; i < 16; i++) e[i] = min(e[i], e[i + 16]);
            #pragma unroll
            for (int i = 0; i < 8; i++)  e[i] = min(e[i], e[i + 8]);
            #pragma unroll
            for (int i = 0; i < 4; i++)  e[i] = min(e[i], e[i + 4]);
            const int idx = min(min(e[0], e[2]), min(e[1], e[3]));
            // merge with partner lane -> both lanes hold identical (bAll, bi)
            const float vo = __shfl_xor_sync(0xffffffffu, bm, 1);
            const int   io = __shfl_xor_sync(0xffffffffu, idx, 1);
            const float bAll = fmaxf(bm, vo);
            const int bi = min((bm == bAll) ? idx : BIGI, (vo == bAll) ? io : BIGI);
            // branchless epilogue: both threads store identical values
            const int bit = (mkb[t >> 5] >> (t & 31)) & 1;
            sm.v.bp[(t - 1) * NN + j] = (unsigned char)(bit ? bi : j);
            if (bit) alpha = bAll + ecur;
            sm.v.alphaS[cb][j] = alpha;
            ecur = enext;
            if (t + 2 < TT) enext = srow[(size_t)(t + 2) * NN];
            __syncthreads();
        }
        if (tid == 0) {
            const int fb = (TT - 1) & 1;
            float bestf = -1e30f; int cur = 0;
            for (int jj = 0; jj < NN; jj++) {
                float vv = sm.v.alphaS[fb][jj] + endv[jj];
                if (vv > bestf) { bestf = vv; cur = jj; }
            }
            sm.v.tag[TT - 1] = cur;
            for (int t = TT - 1; t >= 1; t--) {
                cur = sm.v.bp[(t - 1) * NN + cur];
                sm.v.tag[t - 1] = cur;
            }
        }
        __syncthreads();
        for (int t = tid; t < TT; t += 128) {
            const int bit = (mkb[t >> 5] >> (t & 31)) & 1;
            out_tags[b * TT + t] = (float)(sm.v.tag[t] * bit);
        }
    }
}

extern "C" void kernel_launch(void* const* d_in, const int* in_sizes, int n_in,
                              void* d_out, int out_size) {
    const float* X      = (const float*)d_in[0];
    const int*   mask   = (const int*)d_in[1];
    const int*   labels = (const int*)d_in[2];
    const float* W      = (const float*)d_in[3];
    const float* bias   = (const float*)d_in[4];
    const float* trans  = (const float*)d_in[5];
    const float* startv = (const float*)d_in[6];
    const float* endv   = (const float*)d_in[7];
    float* out = (float*)d_out;

    gemm_f32x2_kernel<<<512, 128>>>(X, W, out, out + LOSS_OFF);
    reduce_kernel<<<SCORES_ELEMS / 4 / 256, 256>>>(bias, mask, out);
    crf_kernel<<<128, 128>>>(out, mask, labels, trans, startv, endv,
                             out + TAGS_OFF, out + LOSS_OFF);
}

// round 13
// speedup vs baseline: 1.2701x; 1.1146x over previous
#include <cuda_runtime.h>
#include <cstddef>

#define BB 64
#define TT 512
#define DD 1024
#define NN 64
#define SCORES_ELEMS (BB*TT*NN)
#define TAGS_OFF SCORES_ELEMS
#define LOSS_OFF (SCORES_ELEMS + BB*TT)

#define L2E 1.4426950408889634f
#define LN2 0.6931471805599453f

__device__ float g_logz[BB];
__device__ float g_gold[BB];
__device__ __align__(16) float g_part[3][SCORES_ELEMS];   // split-K partials (24MB)

__device__ __forceinline__ float fast_ex2(float x){ float r; asm("ex2.approx.ftz.f32 %0, %1;" : "=f"(r) : "f"(x)); return r; }
__device__ __forceinline__ float fast_lg2(float x){ float r; asm("lg2.approx.ftz.f32 %0, %1;" : "=f"(r) : "f"(x)); return r; }

typedef unsigned long long ull;
__device__ __forceinline__ ull pk2(float x, float y){ ull r; asm("mov.b64 %0, {%1,%2};" : "=l"(r) : "f"(x), "f"(y)); return r; }
__device__ __forceinline__ void upk2(ull v, float& x, float& y){ asm("mov.b64 {%0,%1}, %2;" : "=f"(x), "=f"(y) : "l"(v)); }
__device__ __forceinline__ ull ffma2(ull a, ull b, ull c){ ull d; asm("fma.rn.f32x2 %0, %1, %2, %3;" : "=l"(d) : "l"(a), "l"(b), "l"(c)); return d; }

__device__ __forceinline__ void barV(){ asm volatile("bar.sync 1, 128;" ::: "memory"); }  // viterbi
__device__ __forceinline__ void barL(){ asm volatile("bar.sync 2, 64;"  ::: "memory"); }  // lse
__device__ __forceinline__ void barG(){ asm volatile("bar.sync 3, 64;"  ::: "memory"); }  // gold

// ---------------------------------------------------------------------------
// Split-K(x4) GEMM with f32x2 dual-FMA, KC=16, grid 1024 -> 4 CTAs/SM wave.
// blockIdx = rowtile*4 + split. Each CTA: 128 rows x 64 cols, K-range
// [split*256, +256). split0 -> out, split s -> g_part[s-1].
// ---------------------------------------------------------------------------
#define KC 16
#define KSPLIT 256
#define NCHUNK (KSPLIT/KC)

__global__ __launch_bounds__(128, 4) void gemm_f32x2_kernel(
    const float* __restrict__ X, const float* __restrict__ W,
    float* __restrict__ out, float* __restrict__ out_loss)
{
    __shared__ __align__(16) float As[2][KC][128];   // 16384 B
    __shared__ __align__(16) float Ws[2][KC][64];    // 8192 B

    const int tid = threadIdx.x;
    const int split = blockIdx.x & 3;
    const int rowtile = blockIdx.x >> 2;
    const int rowbase = rowtile * 128;
    const int kbase = split * KSPLIT;

    if (blockIdx.x == 0 && tid == 0) *out_loss = 0.f;

    const int rg = tid >> 3;        // 0..15
    const int cg = tid & 7;         // 0..7
    const int r8 = rg * 8, c8 = cg * 8;

    const float* Xrow = X + (size_t)(rowbase + tid) * DD + kbase;
    const int kr = tid >> 3;            // 0..15
    const int wsoff = (tid & 7) * 8;    // 0..56
    const float* Wbase = W + (size_t)(kbase + kr) * NN + wsoff;

    float4 xa[4], wb[2];

    ull acc[8][4];
    #pragma unroll
    for (int r = 0; r < 8; r++)
        #pragma unroll
        for (int p = 0; p < 4; p++) acc[r][p] = 0ULL;

    // prologue: chunk 0
    #pragma unroll
    for (int q = 0; q < 4; q++) xa[q] = *(const float4*)&Xrow[q * 4];
    #pragma unroll
    for (int e = 0; e < 2; e++) wb[e] = *(const float4*)&Wbase[e * 4];
    #pragma unroll
    for (int q = 0; q < 4; q++) {
        As[0][q*4+0][tid] = xa[q].x; As[0][q*4+1][tid] = xa[q].y;
        As[0][q*4+2][tid] = xa[q].z; As[0][q*4+3][tid] = xa[q].w;
    }
    #pragma unroll
    for (int e = 0; e < 2; e++) *(float4*)&Ws[0][kr][wsoff + e * 4] = wb[e];
    __syncthreads();

    for (int c = 0; c < NCHUNK; c++) {
        if (c + 1 < NCHUNK) {
            const int kk = (c + 1) * KC;
            #pragma unroll
            for (int q = 0; q < 4; q++) xa[q] = *(const float4*)&Xrow[kk + q * 4];
            #pragma unroll
            for (int e = 0; e < 2; e++) wb[e] = *(const float4*)&Wbase[(size_t)kk * NN + e * 4];
        }
        const int buf = c & 1;
        #pragma unroll 8
        for (int k = 0; k < KC; k++) {
            float4 a0 = *(const float4*)&As[buf][k][r8];
            float4 a1 = *(const float4*)&As[buf][k][r8 + 4];
            ulonglong2 w0 = *(const ulonglong2*)&Ws[buf][k][c8];
            ulonglong2 w1 = *(const ulonglong2*)&Ws[buf][k][c8 + 4];
            ull A[8];
            A[0] = pk2(a0.x, a0.x); A[1] = pk2(a0.y, a0.y);
            A[2] = pk2(a0.z, a0.z); A[3] = pk2(a0.w, a0.w);
            A[4] = pk2(a1.x, a1.x); A[5] = pk2(a1.y, a1.y);
            A[6] = pk2(a1.z, a1.z); A[7] = pk2(a1.w, a1.w);
            #pragma unroll
            for (int r = 0; r < 8; r++) {
                acc[r][0] = ffma2(A[r], w0.x, acc[r][0]);
                acc[r][1] = ffma2(A[r], w0.y, acc[r][1]);
                acc[r][2] = ffma2(A[r], w1.x, acc[r][2]);
                acc[r][3] = ffma2(A[r], w1.y, acc[r][3]);
            }
        }
        if (c + 1 < NCHUNK) {
            const int nb = (c + 1) & 1;
            #pragma unroll
            for (int q = 0; q < 4; q++) {
                As[nb][q*4+0][tid] = xa[q].x; As[nb][q*4+1][tid] = xa[q].y;
                As[nb][q*4+2][tid] = xa[q].z; As[nb][q*4+3][tid] = xa[q].w;
            }
            #pragma unroll
            for (int e = 0; e < 2; e++) *(float4*)&Ws[nb][kr][wsoff + e * 4] = wb[e];
            __syncthreads();
        }
    }

    float* dst = split ? g_part[split - 1] : out;
    #pragma unroll
    for (int r = 0; r < 8; r++) {
        const int row = rowbase + r8 + r;
        float v[8];
        upk2(acc[r][0], v[0], v[1]); upk2(acc[r][1], v[2], v[3]);
        upk2(acc[r][2], v[4], v[5]); upk2(acc[r][3], v[6], v[7]);
        float4 o0 = { v[0], v[1], v[2], v[3] };
        float4 o1 = { v[4], v[5], v[6], v[7] };
        *(float4*)&dst[(size_t)row * NN + c8]     = o0;
        *(float4*)&dst[(size_t)row * NN + c8 + 4] = o1;
    }
}

// out = (out + p0 + p1 + p2 + bias) * mask   (524288 float4s)
__global__ __launch_bounds__(256) void reduce_kernel(
    const float* __restrict__ bias, const int* __restrict__ mask,
    float* __restrict__ out)
{
    const int i = blockIdx.x * 256 + threadIdx.x;     // float4 index
    float4 a  = ((const float4*)out)[i];
    float4 p0 = ((const float4*)g_part[0])[i];
    float4 p1 = ((const float4*)g_part[1])[i];
    float4 p2 = ((const float4*)g_part[2])[i];
    const int row = i >> 4;
    const float mf = (float)mask[row];
    const int c4 = (i & 15) * 4;
    float4 bv = *(const float4*)&bias[c4];
    float4 o;
    o.x = ((a.x + p0.x) + (p1.x + p2.x) + bv.x) * mf;
    o.y = ((a.y + p0.y) + (p1.y + p2.y) + bv.y) * mf;
    o.z = ((a.z + p0.z) + (p1.z + p2.z) + bv.z) * mf;
    o.w = ((a.w + p0.w) + (p1.w + p2.w) + bv.w) * mf;
    ((float4*)out)[i] = o;
}

// ---------------------------------------------------------------------------
// CRF kernel: 64 CTAs x 256 threads — one CTA per batch, all three recurrences
// co-located so every SMSP interleaves a Viterbi warp with an LSE/gold warp.
//   tid   0-127: Viterbi (bar 1,128)     [wid 0-3 -> SMSP 0-3]
//   tid 128-191: log-partition (bar 2,64)[wid 4-5 -> SMSP 0-1]
//   tid 192-255: gold score (bar 3,64)   [wid 6-7 -> SMSP 2-3]
// Final __syncthreads -> fused loss atomic.
// ---------------------------------------------------------------------------
struct CrfSmAll {
    unsigned char bp[(TT - 1) * NN];   // 32704
    float alphaS[2][NN];
    int   tag[TT];
    float pS[2][NN];
    float redf[2];
    int   redi[2];
    float logz_s, gold_s;
};

#define BIGI 0x7fffffff

__global__ __launch_bounds__(256) void crf_kernel(
    const float* __restrict__ scores, const int* __restrict__ mask,
    const int* __restrict__ labels, const float* __restrict__ trans,
    const float* __restrict__ startv, const float* __restrict__ endv,
    float* __restrict__ out_tags, float* __restrict__ out_loss)
{
    __shared__ __align__(16) CrfSmAll sm;
    const int tid = threadIdx.x;
    const int b = blockIdx.x;

    if (tid < 128) {
        // ===== VITERBI: 2 thr/tag, tree argmax, branchless epilogue =========
        const int j = tid >> 1;
        const int h = tid & 1;
        const int i0 = h * 32;

        unsigned mkb[TT/32];
        #pragma unroll
        for (int w = 0; w < TT/32; w++)
            mkb[w] = __ballot_sync(0xffffffffu, mask[b * TT + w * 32 + (tid & 31)] != 0);

        float Tr[32];
        #pragma unroll
        for (int i = 0; i < 32; i++) Tr[i] = trans[(i0 + i) * NN + j];

        const float* srow = scores + (size_t)b * TT * NN + j;
        float alpha = startv[j] + srow[0];
        sm.alphaS[0][j] = alpha;
        float ecur = srow[NN];
        float enext = srow[2 * NN];
        barV();

        for (int t = 1; t < TT; t++) {
            const int pb = (t - 1) & 1, cb = t & 1;
            float v[32];
            #pragma unroll
            for (int c = 0; c < 8; c++) {
                float4 av = *(const float4*)&sm.alphaS[pb][i0 + c * 4];
                v[c*4+0] = av.x + Tr[c*4+0];
                v[c*4+1] = av.y + Tr[c*4+1];
                v[c*4+2] = av.z + Tr[c*4+2];
                v[c*4+3] = av.w + Tr[c*4+3];
            }
            float m16[16], m8[8], m4[4], m2[2];
            #pragma unroll
            for (int i = 0; i < 16; i++) m16[i] = fmaxf(v[i], v[i + 16]);
            #pragma unroll
            for (int i = 0; i < 8; i++)  m8[i] = fmaxf(m16[i], m16[i + 8]);
            #pragma unroll
            for (int i = 0; i < 4; i++)  m4[i] = fmaxf(m8[i], m8[i + 4]);
            m2[0] = fmaxf(m4[0], m4[2]); m2[1] = fmaxf(m4[1], m4[3]);
            const float bm = fmaxf(m2[0], m2[1]);
            int e[32];
            #pragma unroll
            for (int i = 0; i < 32; i++) e[i] = (v[i] == bm) ? (i0 + i) : BIGI;
            #pragma unroll
            for (int i = 0; i < 16; i++) e[i] = min(e[i], e[i + 16]);
            #pragma unroll
            for (int i = 0; i < 8; i++)  e[i] = min(e[i], e[i + 8]);
            #pragma unroll
            for (int i = 0; i < 4; i++)  e[i] = min(e[i], e[i + 4]);
            const int idx = min(min(e[0], e[2]), min(e[1], e[3]));
            const float vo = __shfl_xor_sync(0xffffffffu, bm, 1);
            const int   io = __shfl_xor_sync(0xffffffffu, idx, 1);
            const float bAll = fmaxf(bm, vo);
            const int bi = min((bm == bAll) ? idx : BIGI, (vo == bAll) ? io : BIGI);
            const int bit = (mkb[t >> 5] >> (t & 31)) & 1;
            sm.bp[(t - 1) * NN + j] = (unsigned char)(bit ? bi : j);
            if (bit) alpha = bAll + ecur;
            sm.alphaS[cb][j] = alpha;
            ecur = enext;
            if (t + 2 < TT) enext = srow[(size_t)(t + 2) * NN];
            barV();
        }
        if (tid == 0) {
            const int fb = (TT - 1) & 1;
            float bestf = -1e30f; int cur = 0;
            for (int jj = 0; jj < NN; jj++) {
                float vv = sm.alphaS[fb][jj] + endv[jj];
                if (vv > bestf) { bestf = vv; cur = jj; }
            }
            sm.tag[TT - 1] = cur;
            for (int t = TT - 1; t >= 1; t--) {
                cur = sm.bp[(t - 1) * NN + cur];
                sm.tag[t - 1] = cur;
            }
        }
        barV();
        for (int t = tid; t < TT; t += 128) {
            const int bit = (mkb[t >> 5] >> (t & 31)) & 1;
            out_tags[b * TT + t] = (float)(sm.tag[t] * bit);
        }
    } else if (tid < 192) {
        // ===== LOG PARTITION (1 thread/tag, f32x2 matvec, 1 bar/step) =======
        const int j = tid - 128;
        unsigned mkb[TT/32];
        #pragma unroll
        for (int w = 0; w < TT/32; w++)
            mkb[w] = __ballot_sync(0xffffffffu, mask[b * TT + w * 32 + (tid & 31)] != 0);

        ull E2[NN/2];
        #pragma unroll
        for (int i2 = 0; i2 < NN/2; i2++) {
            float e0 = fast_ex2(trans[(2*i2)     * NN + j] * L2E);
            float e1 = fast_ex2(trans[(2*i2 + 1) * NN + j] * L2E);
            E2[i2] = pk2(e0, e1);
        }

        const float* srow = scores + (size_t)b * TT * NN + j;
        float alpha = startv[j] + srow[0];
        const float m0 = startv[0] + scores[(size_t)b * TT * NN];
        float Mref = m0;
        sm.pS[0][j] = fast_ex2((alpha - m0) * L2E);

        float ecur = srow[NN];
        float enext = srow[2 * NN];
        barL();

        for (int t = 1; t < TT; t++) {
            const int pb = (t - 1) & 1, cb = t & 1;
            float p0 = sm.pS[pb][0];
            const float mNew = fmaf(fast_lg2(p0), LN2, Mref);   // alpha0^(t-1)
            ull a0 = 0ULL, a1 = 0ULL, a2 = 0ULL, a3 = 0ULL;
            #pragma unroll
            for (int i = 0; i < NN; i += 8) {
                ulonglong2 q0 = *(const ulonglong2*)&sm.pS[pb][i];
                ulonglong2 q1 = *(const ulonglong2*)&sm.pS[pb][i + 4];
                a0 = ffma2(q0.x, E2[i/2],     a0);
                a1 = ffma2(q0.y, E2[i/2 + 1], a1);
                a2 = ffma2(q1.x, E2[i/2 + 2], a2);
                a3 = ffma2(q1.y, E2[i/2 + 3], a3);
            }
            float f0,f1,f2,f3,f4,f5,f6,f7;
            upk2(a0,f0,f1); upk2(a1,f2,f3); upk2(a2,f4,f5); upk2(a3,f6,f7);
            float s = ((f0+f1)+(f2+f3)) + ((f4+f5)+(f6+f7));
            float cand = fmaf(fast_lg2(s), LN2, Mref) + ecur;
            const int bit = (mkb[t >> 5] >> (t & 31)) & 1;
            if (bit) alpha = cand;
            sm.pS[cb][j] = fast_ex2((alpha - mNew) * L2E);
            Mref = mNew;
            ecur = enext;
            if (t + 2 < TT) enext = srow[(size_t)(t + 2) * NN];
            barL();
        }
        sm.pS[0][j] = alpha + endv[j];
        barL();
        if (j < 32) {
            float v0 = sm.pS[0][j], v1 = sm.pS[0][j + 32];
            float m2 = sm.pS[0][0];
            float ss = fast_ex2((v0 - m2) * L2E) + fast_ex2((v1 - m2) * L2E);
            #pragma unroll
            for (int off = 16; off; off >>= 1) ss += __shfl_xor_sync(0xffffffffu, ss, off);
            if (j == 0) {
                float lz = fmaf(fast_lg2(ss), LN2, m2);
                g_logz[b] = lz;
                sm.logz_s = lz;
            }
        }
    } else {
        // ===== GOLD SCORE (threads 192..255) ================================
        const int gt = tid - 192;
        float acc = 0.f; int cnt = 0;
        for (int t = gt; t < TT; t += 64) {
            const int mkv = mask[b * TT + t];
            const int lt = labels[b * TT + t];
            const float mf = (float)mkv;
            acc += scores[((size_t)(b * TT + t)) * NN + lt] * mf;
            if (t > 0) {
                const int lp = labels[b * TT + t - 1];
                acc += trans[lp * NN + lt] * mf;
            }
            cnt += mkv;
        }
        #pragma unroll
        for (int off = 16; off; off >>= 1) {
            acc += __shfl_xor_sync(0xffffffffu, acc, off);
            cnt += __shfl_xor_sync(0xffffffffu, cnt, off);
        }
        if ((gt & 31) == 0) { sm.redf[gt >> 5] = acc; sm.redi[gt >> 5] = cnt; }
        barG();
        if (gt == 0) {
            float a = sm.redf[0] + sm.redf[1];
            int c = sm.redi[0] + sm.redi[1];
            float gd = a + startv[labels[b * TT]] + endv[labels[b * TT + c - 1]];
            g_gold[b] = gd;
            sm.gold_s = gd;
        }
    }
    __syncthreads();
    if (tid == 0)
        atomicAdd(out_loss, (sm.logz_s - sm.gold_s) * (1.0f / 64.0f));
}

extern "C" void kernel_launch(void* const* d_in, const int* in_sizes, int n_in,
                              void* d_out, int out_size) {
    const float* X      = (const float*)d_in[0];
    const int*   mask   = (const int*)d_in[1];
    const int*   labels = (const int*)d_in[2];
    const float* W      = (const float*)d_in[3];
    const float* bias   = (const float*)d_in[4];
    const float* trans  = (const float*)d_in[5];
    const float* startv = (const float*)d_in[6];
    const float* endv   = (const float*)d_in[7];
    float* out = (float*)d_out;

    gemm_f32x2_kernel<<<1024, 128>>>(X, W, out, out + LOSS_OFF);
    reduce_kernel<<<SCORES_ELEMS / 4 / 256, 256>>>(bias, mask, out);
    crf_kernel<<<64, 256>>>(out, mask, labels, trans, startv, endv,
                            out + TAGS_OFF, out + LOSS_OFF);
}